// round 15
// baseline (speedup 1.0000x reference)
#include <cuda_runtime.h>
#include <cuda_bf16.h>
#include <cstdint>

// Problem constants
#define BATCH 8
#define NQ    2048
#define NS    4096
#define DIM   512

// Fully fused single kernel. 128 blocks (batch x 16 q-tiles), 512 threads =
// two independent 256-thread pipelines. Support normalization is spread:
// block (b,qt) normalizes s-tile qt upfront and s-tile 16+qt inside the
// mainloop (hidden under other blocks' compute), with epoch-versioned flags.
#define BM 128
#define BN 128
#define BK 64
#define GCHUNK 128
#define NBUF 3
#define NTHREADS 512
#define GRID (BATCH * (NQ / BM))     // 128

#define A_BYTES    (BM * DIM * 2)              // 131072 = 8 chunks of 16KB
#define BBUF_BYTES (BN * BK * 2)               // 16384
#define RM_OFF     (A_BYTES + 2 * NBUF * BBUF_BYTES)   // 229376
#define SMEM_TOTAL (RM_OFF + BM * 4)                   // 229888

// Device scratch
__device__ __nv_bfloat16 g_sn[(size_t)BATCH * NS * DIM];
__device__ unsigned g_flag[BATCH * 32];   // per-s-tile ready flags (+2/replay)
__device__ unsigned g_epoch;              // replay counter
__device__ unsigned g_done;               // block done counter
__device__ float    g_acc[BATCH];         // per-batch sum of (1 - rowmax)

// ---------------------------------------------------------------------------
// helpers
// ---------------------------------------------------------------------------
__device__ __forceinline__ uint32_t swz(uint32_t x) {   // SW128: bits[6:4] ^= bits[9:7]
    return x ^ ((x >> 3) & 0x70);
}
__device__ __forceinline__ void cp_async16(uint32_t saddr, const void* gptr) {
    asm volatile("cp.async.cg.shared.global [%0], [%1], 16;\n" :: "r"(saddr), "l"(gptr));
}
__device__ __forceinline__ void cp_commit() {
    asm volatile("cp.async.commit_group;\n" ::: "memory");
}
template <int N>
__device__ __forceinline__ void cp_wait() {
    asm volatile("cp.async.wait_group %0;\n" :: "n"(N) : "memory");
}
__device__ __forceinline__ void bar_g(int id) {
    asm volatile("bar.sync %0, 256;" :: "r"(id) : "memory");
}
__device__ __forceinline__ unsigned fkey(float f) {
    unsigned u = __float_as_uint(f);
    return (u & 0x80000000u) ? ~u : (u | 0x80000000u);
}
__device__ __forceinline__ float funkey(unsigned k) {
    unsigned u = (k & 0x80000000u) ? (k ^ 0x80000000u) : ~k;
    return __uint_as_float(u);
}
__device__ __forceinline__ void spin_flag(const unsigned* f, unsigned target) {
    while (*(volatile const unsigned*)f < target) { }
}

// Warp-wide normalize of one 512-float row -> bf16 (lane owns cols j*32+lane)
__device__ __forceinline__ void normalize_row(const float* __restrict__ rinF,
                                              __nv_bfloat16* __restrict__ orow, int lane)
{
    const float4* rin = reinterpret_cast<const float4*>(rinF);
    float4 v[4];
    float acc = 0.f;
#pragma unroll
    for (int j = 0; j < 4; j++) {
        v[j] = rin[j * 32 + lane];
        acc += v[j].x * v[j].x + v[j].y * v[j].y + v[j].z * v[j].z + v[j].w * v[j].w;
    }
#pragma unroll
    for (int o = 16; o > 0; o >>= 1) acc += __shfl_xor_sync(0xFFFFFFFFu, acc, o);
    float inv = 1.0f / fmaxf(sqrtf(acc), 1e-12f);
#pragma unroll
    for (int j = 0; j < 4; j++) {
        __nv_bfloat162 h0 = __floats2bfloat162_rn(v[j].x * inv, v[j].y * inv);
        __nv_bfloat162 h1 = __floats2bfloat162_rn(v[j].z * inv, v[j].w * inv);
        uint2 pk;
        pk.x = *reinterpret_cast<unsigned*>(&h0);
        pk.y = *reinterpret_cast<unsigned*>(&h1);
        *reinterpret_cast<uint2*>(orow + (size_t)(j * 32 + lane) * 4) = pk;
    }
}

// ---------------------------------------------------------------------------
// B chunk fill (per group): local chunk ci -> s-tile (2*(ci>>3)+gid),
// k-cols [(ci&7)*64, +64). 1024 x 16B segments, 4 per group-thread.
// ---------------------------------------------------------------------------
__device__ __forceinline__ void fill_b_chunk(uint32_t smem_u32,
                                             const __nv_bfloat16* __restrict__ gB,
                                             int ci, int gid, int gtid)
{
    const int st = 2 * (ci >> 3) + gid;
    const int kc = ci & 7;
    const uint32_t bb = A_BYTES
                      + (uint32_t)(gid * NBUF + (ci % NBUF)) * BBUF_BYTES;
#pragma unroll
    for (int i = 0; i < 4; i++) {
        int idx = gtid + i * 256;        // 0..1023
        int r = idx >> 3;                // 8 segs per 128B row
        int s8 = idx & 7;
        const void* src = gB + (size_t)(st * BN + r) * DIM + kc * BK + s8 * 8;
        cp_async16(smem_u32 + bb + swz((uint32_t)(r * 128 + s8 * 16)), src);
    }
    cp_commit();
}

// ---------------------------------------------------------------------------
// Fully fused kernel
// ---------------------------------------------------------------------------
__global__ __launch_bounds__(NTHREADS, 1) void fused_kernel(
    const float* __restrict__ qf, const float* __restrict__ sf,
    float* __restrict__ out)
{
    extern __shared__ char smem[];
    unsigned* rowmaxU = reinterpret_cast<unsigned*>(smem + RM_OFF);
    __shared__ float red[NTHREADS / 32];
    __shared__ unsigned s_last;
    const uint32_t smem_u32 = (uint32_t)__cvta_generic_to_shared(smem);

    const int b   = blockIdx.x >> 4;
    const int qt  = blockIdx.x & 15;
    const int tid = threadIdx.x;
    const int lane = tid & 31;
    const int wid  = tid >> 5;
    const int gid  = wid >> 3;           // warp-group 0 / 1
    const int gtid = tid & 255;
    const int gwid = wid & 7;
    const int wm = (gwid >> 2) * 64;
    const int wn = (gwid & 3) * 32;

    const unsigned e = *(volatile unsigned*)&g_epoch;
    const unsigned target = 2u * (e + 1u);

    // ---- upfront: normalize s-tile qt of batch b (128 rows), set flag ----
    {
        const float* gS = sf + ((size_t)b * NS + (size_t)qt * BN) * DIM;
        __nv_bfloat16* oS = g_sn + ((size_t)b * NS + (size_t)qt * BN) * DIM;
#pragma unroll
        for (int rr = 0; rr < 8; rr++) {
            int r = wid * 8 + rr;
            normalize_row(gS + (size_t)r * DIM, oS + (size_t)r * DIM, lane);
        }
    }
    __syncthreads();
    if (tid == 0) {
        __threadfence();
        atomicAdd(&g_flag[b * 32 + qt], 2u);
    }

    if (tid < BM) rowmaxU[tid] = 0u;

    // ---- A tile: normalize 128 q-rows fp32 -> bf16 into swizzled smem ----
    {
        const float* gQ = qf + (size_t)(b * NQ + qt * BM) * DIM;
        const int ch = lane >> 2;            // 64-col chunk 0..7
        const int s8 = (lane & 3) * 2;       // first 16B seg within chunk
#pragma unroll
        for (int rr = 0; rr < 8; rr++) {
            int r = wid * 8 + rr;
            const float4* rin = reinterpret_cast<const float4*>(gQ + (size_t)r * DIM);
            float4 v[4];
            float acc = 0.f;
#pragma unroll
            for (int j = 0; j < 4; j++) {
                v[j] = rin[lane * 4 + j];
                acc += v[j].x * v[j].x + v[j].y * v[j].y
                     + v[j].z * v[j].z + v[j].w * v[j].w;
            }
#pragma unroll
            for (int o = 16; o > 0; o >>= 1)
                acc += __shfl_xor_sync(0xFFFFFFFFu, acc, o);
            float inv = 1.0f / fmaxf(sqrtf(acc), 1e-12f);

            unsigned pk[8];
#pragma unroll
            for (int j = 0; j < 4; j++) {
                __nv_bfloat162 h0 = __floats2bfloat162_rn(v[j].x * inv, v[j].y * inv);
                __nv_bfloat162 h1 = __floats2bfloat162_rn(v[j].z * inv, v[j].w * inv);
                pk[2 * j]     = *reinterpret_cast<unsigned*>(&h0);
                pk[2 * j + 1] = *reinterpret_cast<unsigned*>(&h1);
            }
            uint4 q0 = make_uint4(pk[0], pk[1], pk[2], pk[3]);
            uint4 q1 = make_uint4(pk[4], pk[5], pk[6], pk[7]);
            *reinterpret_cast<uint4*>(smem + ch * 16384
                + swz((uint32_t)(r * 128 + s8 * 16))) = q0;
            *reinterpret_cast<uint4*>(smem + ch * 16384
                + swz((uint32_t)(r * 128 + (s8 + 1) * 16))) = q1;
        }
    }

    const __nv_bfloat16* gB = g_sn + (size_t)b * NS * DIM;

    // prologue: wait for own first tile, then fills for chunks 0, 1
    spin_flag(&g_flag[b * 32 + gid], target);
    fill_b_chunk(smem_u32, gB, 0, gid, gtid);
    fill_b_chunk(smem_u32, gB, 1, gid, gtid);
    __syncthreads();                     // A + rowmax init visible to all

    float C[4][4][4];
#pragma unroll
    for (int mi = 0; mi < 4; mi++)
#pragma unroll
        for (int ni = 0; ni < 4; ni++)
#pragma unroll
            for (int e2 = 0; e2 < 4; e2++) C[mi][ni][e2] = 0.f;

    float rmax[4][2];
#pragma unroll
    for (int t = 0; t < 4; t++) { rmax[t][0] = -1e30f; rmax[t][1] = -1e30f; }

    for (int ci = 0; ci < GCHUNK; ci++) {
        if (ci < GCHUNK - 1) cp_wait<1>(); else cp_wait<0>();
        bar_g(1 + gid);
        if (ci + 2 < GCHUNK) {
            if (((ci + 2) & 7) == 0) {
                int st2 = 2 * ((ci + 2) >> 3) + gid;
                spin_flag(&g_flag[b * 32 + st2], target);
            }
            fill_b_chunk(smem_u32, gB, ci + 2, gid, gtid);
        }

        const int kc = ci & 7;           // A chunk index for this k-range
        const uint32_t bb = A_BYTES
                          + (uint32_t)(gid * NBUF + (ci % NBUF)) * BBUF_BYTES;

#pragma unroll
        for (int ksp = 0; ksp < 2; ksp++) {
            unsigned bfr[4][4];
            {
                const uint32_t kb = (uint32_t)(ksp * 64
                                  + ((lane >> 3) & 1) * 16 + (lane >> 4) * 32);
#pragma unroll
                for (int ni = 0; ni < 4; ni++) {
                    int n = wn + ni * 8 + (lane & 7);
                    uint32_t addr = smem_u32 + bb + swz((uint32_t)(n * 128) + kb);
                    asm volatile("ldmatrix.sync.aligned.m8n8.x4.shared.b16 {%0,%1,%2,%3}, [%4];"
                                 : "=r"(bfr[ni][0]), "=r"(bfr[ni][1]),
                                   "=r"(bfr[ni][2]), "=r"(bfr[ni][3])
                                 : "r"(addr));
                }
            }
#pragma unroll
            for (int h = 0; h < 2; h++) {
                const int ks = ksp * 2 + h;
                const uint32_t kb = (uint32_t)(ks * 32 + (lane >> 4) * 16);
                unsigned af[4][4];
#pragma unroll
                for (int mi = 0; mi < 4; mi++) {
                    int r0 = wm + mi * 16 + (lane & 15);
                    uint32_t addr = smem_u32 + kc * 16384
                                  + swz((uint32_t)(r0 * 128) + kb);
                    asm volatile("ldmatrix.sync.aligned.m8n8.x4.shared.b16 {%0,%1,%2,%3}, [%4];"
                                 : "=r"(af[mi][0]), "=r"(af[mi][1]),
                                   "=r"(af[mi][2]), "=r"(af[mi][3])
                                 : "r"(addr));
                }
#pragma unroll
                for (int mi = 0; mi < 4; mi++)
#pragma unroll
                    for (int ni = 0; ni < 4; ni++) {
                        asm volatile(
                            "mma.sync.aligned.m16n8k16.row.col.f32.bf16.bf16.f32 "
                            "{%0,%1,%2,%3}, {%4,%5,%6,%7}, {%8,%9}, {%0,%1,%2,%3};"
                            : "+f"(C[mi][ni][0]), "+f"(C[mi][ni][1]),
                              "+f"(C[mi][ni][2]), "+f"(C[mi][ni][3])
                            : "r"(af[mi][0]), "r"(af[mi][1]),
                              "r"(af[mi][2]), "r"(af[mi][3]),
                              "r"(bfr[ni][2 * h]), "r"(bfr[ni][2 * h + 1]));
                    }
            }
        }

        if (kc == 7) {   // end of s-tile: fold into running row max, reset C
#pragma unroll
            for (int mi = 0; mi < 4; mi++) {
                float m0 = rmax[mi][0], m1 = rmax[mi][1];
#pragma unroll
                for (int ni = 0; ni < 4; ni++) {
                    m0 = fmaxf(m0, fmaxf(C[mi][ni][0], C[mi][ni][1]));
                    m1 = fmaxf(m1, fmaxf(C[mi][ni][2], C[mi][ni][3]));
                    C[mi][ni][0] = 0.f; C[mi][ni][1] = 0.f;
                    C[mi][ni][2] = 0.f; C[mi][ni][3] = 0.f;
                }
                rmax[mi][0] = m0; rmax[mi][1] = m1;
            }
        }

        // mid-loop: normalize s-tile 16+qt (64 rows per group), hidden under
        // other blocks' compute; earliest consumer needs it at ci ~ 62.
        if (ci == 15) {
            const int t2 = 16 + qt;
            const float* gS2 = sf + ((size_t)b * NS + (size_t)t2 * BN
                                     + (size_t)gid * 64) * DIM;
            __nv_bfloat16* oS2 = g_sn + ((size_t)b * NS + (size_t)t2 * BN
                                         + (size_t)gid * 64) * DIM;
#pragma unroll
            for (int rr = 0; rr < 8; rr++) {
                int r = gwid * 8 + rr;
                normalize_row(gS2 + (size_t)r * DIM, oS2 + (size_t)r * DIM, lane);
            }
            bar_g(1 + gid);
            if (gtid == 0) {
                __threadfence();
                atomicAdd(&g_flag[b * 32 + t2], 1u);
            }
        }
    }

    // epilogue: per-row max across warps/groups via smem atomics
#pragma unroll
    for (int t = 0; t < 4; t++) {
#pragma unroll
        for (int g = 0; g < 2; g++) {
            int row = wm + t * 16 + (lane >> 2) + g * 8;
            atomicMax(&rowmaxU[row], fkey(rmax[t][g]));
        }
    }
    __syncthreads();

    // block sum of (1 - rowmax) -> g_acc[b]; last block writes out + resets
    float v = 0.f;
    if (tid < BM) v = 1.0f - funkey(rowmaxU[tid]);
#pragma unroll
    for (int o = 16; o > 0; o >>= 1) v += __shfl_xor_sync(0xFFFFFFFFu, v, o);
    if (lane == 0) red[wid] = v;
    __syncthreads();
    if (wid == 0) {
        float sum = (lane < NTHREADS / 32) ? red[lane] : 0.f;
#pragma unroll
        for (int o = 8; o > 0; o >>= 1) sum += __shfl_xor_sync(0xFFFFFFFFu, sum, o);
        if (lane == 0) atomicAdd(&g_acc[b], sum);
    }
    __threadfence();
    __syncthreads();
    if (tid == 0)
        s_last = (atomicAdd(&g_done, 1u) == GRID - 1) ? 1u : 0u;
    __syncthreads();
    if (s_last) {
        __threadfence();
        if (tid < BATCH) {
            float a = *(volatile float*)&g_acc[tid];
            out[tid] = a * (1.0f / NQ);
            *(volatile float*)&g_acc[tid] = 0.f;
        }
        if (tid == 0) {
            *(volatile unsigned*)&g_done = 0u;
            *(volatile unsigned*)&g_epoch = e + 1u;
        }
    }
}

// ---------------------------------------------------------------------------
extern "C" void kernel_launch(void* const* d_in, const int* in_sizes, int n_in,
                              void* d_out, int out_size)
{
    const float* q = (const float*)d_in[0];
    const float* s = (const float*)d_in[1];
    float* out = (float*)d_out;

    cudaFuncSetAttribute(fused_kernel,
                         cudaFuncAttributeMaxDynamicSharedMemorySize, SMEM_TOTAL);

    fused_kernel<<<GRID, NTHREADS, SMEM_TOTAL>>>(q, s, out);
}

// round 17
// speedup vs baseline: 1.1623x; 1.1623x over previous
#include <cuda_runtime.h>
#include <cuda_bf16.h>
#include <cstdint>

// Problem constants
#define BATCH 8
#define NQ    2048
#define NS    4096
#define DIM   512

// Tiling: two independent 256-thread groups per CTA (own named barrier, own
// B ring), group g handles s-tiles g, g+2, ... A (128x512 bf16) resident,
// normalized IN-KERNEL from fp32 query (no global bf16 round-trip for A).
#define BM 128
#define BN 128
#define BK 64
#define GCHUNK 128
#define NBUF 3
#define NTHREADS 512

#define A_BYTES    (BM * DIM * 2)              // 131072 = 8 chunks of 16KB
#define BBUF_BYTES (BN * BK * 2)               // 16384
#define RM_OFF     (A_BYTES + 2 * NBUF * BBUF_BYTES)   // 229376
#define SMEM_TOTAL (RM_OFF + BM * 4)                   // 229888

// Device scratch (support only; query is normalized inside the GEMM)
__device__ __nv_bfloat16 g_sn[(size_t)BATCH * NS * DIM];

// ---------------------------------------------------------------------------
// helpers
// ---------------------------------------------------------------------------
__device__ __forceinline__ uint32_t swz(uint32_t x) {   // SW128: bits[6:4] ^= bits[9:7]
    return x ^ ((x >> 3) & 0x70);
}
__device__ __forceinline__ void cp_async16(uint32_t saddr, const void* gptr) {
    asm volatile("cp.async.cg.shared.global [%0], [%1], 16;\n" :: "r"(saddr), "l"(gptr));
}
__device__ __forceinline__ void cp_commit() {
    asm volatile("cp.async.commit_group;\n" ::: "memory");
}
template <int N>
__device__ __forceinline__ void cp_wait() {
    asm volatile("cp.async.wait_group %0;\n" :: "n"(N) : "memory");
}
__device__ __forceinline__ void bar_g(int id) {
    asm volatile("bar.sync %0, 256;" :: "r"(id) : "memory");
}
__device__ __forceinline__ unsigned fkey(float f) {
    unsigned u = __float_as_uint(f);
    return (u & 0x80000000u) ? ~u : (u | 0x80000000u);
}
__device__ __forceinline__ float funkey(unsigned k) {
    unsigned u = (k & 0x80000000u) ? (k ^ 0x80000000u) : ~k;
    return __uint_as_float(u);
}

// ---------------------------------------------------------------------------
// Support normalize: one warp per TWO rows (MLP 8: all 8 float4 loads issued
// before the reductions). Also zeroes out[].
// ---------------------------------------------------------------------------
__global__ void normalize_s_kernel(const float* __restrict__ s,
                                   float* __restrict__ out)
{
    if (blockIdx.x == 0 && threadIdx.x < BATCH) out[threadIdx.x] = 0.f;
    int pair = blockIdx.x * (blockDim.x >> 5) + (threadIdx.x >> 5);
    int lane = threadIdx.x & 31;
    int row0 = pair * 2;
    if (row0 >= BATCH * NS) return;

    const float4* r0 = reinterpret_cast<const float4*>(s + (size_t)row0 * DIM);
    const float4* r1 = reinterpret_cast<const float4*>(s + (size_t)(row0 + 1) * DIM);

    float4 a[4], c[4];
#pragma unroll
    for (int j = 0; j < 4; j++) a[j] = r0[j * 32 + lane];
#pragma unroll
    for (int j = 0; j < 4; j++) c[j] = r1[j * 32 + lane];

    float s0 = 0.f, s1 = 0.f;
#pragma unroll
    for (int j = 0; j < 4; j++) {
        s0 += a[j].x * a[j].x + a[j].y * a[j].y + a[j].z * a[j].z + a[j].w * a[j].w;
        s1 += c[j].x * c[j].x + c[j].y * c[j].y + c[j].z * c[j].z + c[j].w * c[j].w;
    }
#pragma unroll
    for (int o = 16; o > 0; o >>= 1) {
        s0 += __shfl_xor_sync(0xFFFFFFFFu, s0, o);
        s1 += __shfl_xor_sync(0xFFFFFFFFu, s1, o);
    }
    float i0 = 1.0f / fmaxf(sqrtf(s0), 1e-12f);
    float i1 = 1.0f / fmaxf(sqrtf(s1), 1e-12f);

    __nv_bfloat16* o0 = g_sn + (size_t)row0 * DIM;
    __nv_bfloat16* o1 = g_sn + (size_t)(row0 + 1) * DIM;
#pragma unroll
    for (int j = 0; j < 4; j++) {
        __nv_bfloat162 h0 = __floats2bfloat162_rn(a[j].x * i0, a[j].y * i0);
        __nv_bfloat162 h1 = __floats2bfloat162_rn(a[j].z * i0, a[j].w * i0);
        uint2 pk;
        pk.x = *reinterpret_cast<unsigned*>(&h0);
        pk.y = *reinterpret_cast<unsigned*>(&h1);
        *reinterpret_cast<uint2*>(o0 + (size_t)(j * 32 + lane) * 4) = pk;
        __nv_bfloat162 g0 = __floats2bfloat162_rn(c[j].x * i1, c[j].y * i1);
        __nv_bfloat162 g1 = __floats2bfloat162_rn(c[j].z * i1, c[j].w * i1);
        uint2 pk2;
        pk2.x = *reinterpret_cast<unsigned*>(&g0);
        pk2.y = *reinterpret_cast<unsigned*>(&g1);
        *reinterpret_cast<uint2*>(o1 + (size_t)(j * 32 + lane) * 4) = pk2;
    }
}

// ---------------------------------------------------------------------------
// B chunk fill (per group): local chunk ci -> s-tile (2*(ci>>3)+gid),
// k-cols [(ci&7)*64, +64). 1024 x 16B segments, 4 per group-thread.
// ---------------------------------------------------------------------------
__device__ __forceinline__ void fill_b_chunk(uint32_t smem_u32,
                                             const __nv_bfloat16* __restrict__ gB,
                                             int ci, int gid, int gtid)
{
    const int st = 2 * (ci >> 3) + gid;
    const int kc = ci & 7;
    const uint32_t bb = A_BYTES
                      + (uint32_t)(gid * NBUF + (ci % NBUF)) * BBUF_BYTES;
#pragma unroll
    for (int i = 0; i < 4; i++) {
        int idx = gtid + i * 256;        // 0..1023
        int r = idx >> 3;                // 8 segs per 128B row
        int s8 = idx & 7;
        const void* src = gB + (size_t)(st * BN + r) * DIM + kc * BK + s8 * 8;
        cp_async16(smem_u32 + bb + swz((uint32_t)(r * 128 + s8 * 16)), src);
    }
    cp_commit();
}

// ---------------------------------------------------------------------------
// GEMM-max: one block per (batch, q-tile), 512 threads = 2 independent
// 256-thread pipelines. A normalized in-prologue from fp32 query.
// ---------------------------------------------------------------------------
__global__ __launch_bounds__(NTHREADS, 1) void gemm_max_kernel(
    const float* __restrict__ qf, float* __restrict__ out)
{
    extern __shared__ char smem[];
    unsigned* rowmaxU = reinterpret_cast<unsigned*>(smem + RM_OFF);
    __shared__ float red[NTHREADS / 32];
    const uint32_t smem_u32 = (uint32_t)__cvta_generic_to_shared(smem);

    const int b   = blockIdx.x >> 4;
    const int qt  = blockIdx.x & 15;
    const int tid = threadIdx.x;
    const int lane = tid & 31;
    const int wid  = tid >> 5;
    const int gid  = wid >> 3;           // warp-group 0 / 1
    const int gtid = tid & 255;
    const int gwid = wid & 7;
    const int wm = (gwid >> 2) * 64;
    const int wn = (gwid & 3) * 32;

    if (tid < BM) rowmaxU[tid] = 0u;

    const __nv_bfloat16* gB = g_sn + (size_t)b * NS * DIM;

    // group prologue: own chunks 0, 1 (issue fills first — mainloop deadline)
    fill_b_chunk(smem_u32, gB, 0, gid, gtid);
    fill_b_chunk(smem_u32, gB, 1, gid, gtid);

    // ---- A tile: normalize 128 q-rows fp32 -> bf16 straight into swizzled
    //      smem. 16 warps x 8 rows; lane owns cols [16*lane, +16). ----
    {
        const float* gQ = qf + (size_t)(b * NQ + qt * BM) * DIM;
        const int ch = lane >> 2;            // 64-col chunk 0..7
        const int s8 = (lane & 3) * 2;       // first 16B seg within chunk
#pragma unroll
        for (int rr = 0; rr < 8; rr++) {
            int r = wid * 8 + rr;
            const float4* rin = reinterpret_cast<const float4*>(gQ + (size_t)r * DIM);
            float4 v[4];
            float acc = 0.f;
#pragma unroll
            for (int j = 0; j < 4; j++) {
                v[j] = rin[lane * 4 + j];    // cols 16*lane + 4j .. +3
                acc += v[j].x * v[j].x + v[j].y * v[j].y
                     + v[j].z * v[j].z + v[j].w * v[j].w;
            }
#pragma unroll
            for (int o = 16; o > 0; o >>= 1)
                acc += __shfl_xor_sync(0xFFFFFFFFu, acc, o);
            float inv = 1.0f / fmaxf(sqrtf(acc), 1e-12f);

            unsigned pk[8];
#pragma unroll
            for (int j = 0; j < 4; j++) {
                __nv_bfloat162 h0 = __floats2bfloat162_rn(v[j].x * inv, v[j].y * inv);
                __nv_bfloat162 h1 = __floats2bfloat162_rn(v[j].z * inv, v[j].w * inv);
                pk[2 * j]     = *reinterpret_cast<unsigned*>(&h0);
                pk[2 * j + 1] = *reinterpret_cast<unsigned*>(&h1);
            }
            uint4 q0 = make_uint4(pk[0], pk[1], pk[2], pk[3]);
            uint4 q1 = make_uint4(pk[4], pk[5], pk[6], pk[7]);
            *reinterpret_cast<uint4*>(smem + ch * 16384
                + swz((uint32_t)(r * 128 + s8 * 16))) = q0;
            *reinterpret_cast<uint4*>(smem + ch * 16384
                + swz((uint32_t)(r * 128 + (s8 + 1) * 16))) = q1;
        }
    }
    __syncthreads();                     // A + rowmax init visible to all

    float C[4][4][4];
#pragma unroll
    for (int mi = 0; mi < 4; mi++)
#pragma unroll
        for (int ni = 0; ni < 4; ni++)
#pragma unroll
            for (int e = 0; e < 4; e++) C[mi][ni][e] = 0.f;

    float rmax[4][2];
#pragma unroll
    for (int t = 0; t < 4; t++) { rmax[t][0] = -1e30f; rmax[t][1] = -1e30f; }

    for (int ci = 0; ci < GCHUNK; ci++) {
        if (ci < GCHUNK - 1) cp_wait<1>(); else cp_wait<0>();
        bar_g(1 + gid);
        if (ci + 2 < GCHUNK) fill_b_chunk(smem_u32, gB, ci + 2, gid, gtid);

        const int kc = ci & 7;           // A chunk index for this k-range
        const uint32_t bb = A_BYTES
                          + (uint32_t)(gid * NBUF + (ci % NBUF)) * BBUF_BYTES;

#pragma unroll
        for (int ksp = 0; ksp < 2; ksp++) {
            unsigned bfr[4][4];
            {
                const uint32_t kb = (uint32_t)(ksp * 64
                                  + ((lane >> 3) & 1) * 16 + (lane >> 4) * 32);
#pragma unroll
                for (int ni = 0; ni < 4; ni++) {
                    int n = wn + ni * 8 + (lane & 7);
                    uint32_t addr = smem_u32 + bb + swz((uint32_t)(n * 128) + kb);
                    asm volatile("ldmatrix.sync.aligned.m8n8.x4.shared.b16 {%0,%1,%2,%3}, [%4];"
                                 : "=r"(bfr[ni][0]), "=r"(bfr[ni][1]),
                                   "=r"(bfr[ni][2]), "=r"(bfr[ni][3])
                                 : "r"(addr));
                }
            }
#pragma unroll
            for (int h = 0; h < 2; h++) {
                const int ks = ksp * 2 + h;
                const uint32_t kb = (uint32_t)(ks * 32 + (lane >> 4) * 16);
                unsigned af[4][4];
#pragma unroll
                for (int mi = 0; mi < 4; mi++) {
                    int r0 = wm + mi * 16 + (lane & 15);
                    uint32_t addr = smem_u32 + kc * 16384
                                  + swz((uint32_t)(r0 * 128) + kb);
                    asm volatile("ldmatrix.sync.aligned.m8n8.x4.shared.b16 {%0,%1,%2,%3}, [%4];"
                                 : "=r"(af[mi][0]), "=r"(af[mi][1]),
                                   "=r"(af[mi][2]), "=r"(af[mi][3])
                                 : "r"(addr));
                }
#pragma unroll
                for (int mi = 0; mi < 4; mi++)
#pragma unroll
                    for (int ni = 0; ni < 4; ni++) {
                        asm volatile(
                            "mma.sync.aligned.m16n8k16.row.col.f32.bf16.bf16.f32 "
                            "{%0,%1,%2,%3}, {%4,%5,%6,%7}, {%8,%9}, {%0,%1,%2,%3};"
                            : "+f"(C[mi][ni][0]), "+f"(C[mi][ni][1]),
                              "+f"(C[mi][ni][2]), "+f"(C[mi][ni][3])
                            : "r"(af[mi][0]), "r"(af[mi][1]),
                              "r"(af[mi][2]), "r"(af[mi][3]),
                              "r"(bfr[ni][2 * h]), "r"(bfr[ni][2 * h + 1]));
                    }
            }
        }

        if (kc == 7) {   // end of s-tile: fold into running row max, reset C
#pragma unroll
            for (int mi = 0; mi < 4; mi++) {
                float m0 = rmax[mi][0], m1 = rmax[mi][1];
#pragma unroll
                for (int ni = 0; ni < 4; ni++) {
                    m0 = fmaxf(m0, fmaxf(C[mi][ni][0], C[mi][ni][1]));
                    m1 = fmaxf(m1, fmaxf(C[mi][ni][2], C[mi][ni][3]));
                    C[mi][ni][0] = 0.f; C[mi][ni][1] = 0.f;
                    C[mi][ni][2] = 0.f; C[mi][ni][3] = 0.f;
                }
                rmax[mi][0] = m0; rmax[mi][1] = m1;
            }
        }
    }

    // epilogue: per-row max across warps/groups via smem atomics
#pragma unroll
    for (int t = 0; t < 4; t++) {
#pragma unroll
        for (int g = 0; g < 2; g++) {
            int row = wm + t * 16 + (lane >> 2) + g * 8;
            atomicMax(&rowmaxU[row], fkey(rmax[t][g]));
        }
    }
    __syncthreads();

    // fused finalize: block sum of (1 - rowmax) -> atomicAdd(out[b], sum/NQ)
    float v = 0.f;
    if (tid < BM) v = 1.0f - funkey(rowmaxU[tid]);
#pragma unroll
    for (int o = 16; o > 0; o >>= 1) v += __shfl_xor_sync(0xFFFFFFFFu, v, o);
    if (lane == 0) red[wid] = v;
    __syncthreads();
    if (wid == 0) {
        float sum = (lane < NTHREADS / 32) ? red[lane] : 0.f;
#pragma unroll
        for (int o = 8; o > 0; o >>= 1) sum += __shfl_xor_sync(0xFFFFFFFFu, sum, o);
        if (lane == 0) atomicAdd(&out[b], sum * (1.0f / NQ));
    }
}

// ---------------------------------------------------------------------------
extern "C" void kernel_launch(void* const* d_in, const int* in_sizes, int n_in,
                              void* d_out, int out_size)
{
    const float* q = (const float*)d_in[0];
    const float* s = (const float*)d_in[1];
    float* out = (float*)d_out;

    cudaFuncSetAttribute(gemm_max_kernel,
                         cudaFuncAttributeMaxDynamicSharedMemorySize, SMEM_TOTAL);

    // 8 warps/block, 2 rows per warp -> 16 rows/block
    normalize_s_kernel<<<(BATCH * NS + 15) / 16, 256>>>(s, out);
    gemm_max_kernel<<<BATCH * (NQ / BM), NTHREADS, SMEM_TOTAL>>>(q, out);
}